// round 13
// baseline (speedup 1.0000x reference)
#include <cuda_runtime.h>
#include <stdint.h>

// Problem constants (fixed by the reference: NX=41, r_max=6.0, voxel=0.3, K=4, min_sep=3)
#define NXG    41
#define NROWS  (NXG * NXG)       // 1681 rows of 41 voxels
#define GVOX   (NXG * NXG * NXG) // 68921
#define KP     4
#define SEP    3
#define NEGF   (-1.0e9f)
#define VTH    (-1.0e8f)

#define HALF0  840               // rows handled by even CTA; odd CTA gets 841
#define MAXP   1024
#define RPITCH 1684

#define THREADS 256
#define NWARP   8
#define ACH     56                               // rows per chunk
#define ANST    3                                // ring stages
#define ACHBUF  (ACH * NXG + 8)                  // 2304 floats = 9216 B (mult 16)

// Shared-memory layout (bytes). Ring buffers are reused as the phase-2 rowmax
// table (6724 B <= 27648 B). Total ~28.5KB -> 7 CTAs/SM at grid=1024.
#define SM_BUF    0                              // 3 * 9216 = 27648 (alias: rowmax)
#define SM_MBAR   (SM_BUF + ANST * ACHBUF * 4)   // 32
#define SM_XS2    (SM_MBAR + 32)                 // 168
#define SM_YS2    (SM_XS2 + 168)
#define SM_ZZ     (SM_YS2 + 168)
#define SM_ROWLO  (SM_ZZ + 168)                  // 848 (own half only)
#define SM_SWV    (SM_ROWLO + 848)               // 32
#define SM_SWR    (SM_SWV + 32)                  // 32
#define SM_PICK   (SM_SWR + 32)
#define SM_PKK    (SM_PICK + 4)
#define SM_PS     (SM_PKK + 4)
#define SM_PG     (SM_PS + 16)
#define SM_PV     (SM_PG + 16)
#define SM_FLAG   (SM_PV + 16)
#define SM_TOTAL  (SM_FLAG + 4 + 28)

// Scratch (no allocation allowed): per-problem row tables + replay-safe tickets.
__device__ float g_rowmax[(size_t)MAXP * RPITCH];
__device__ int   g_ticket[MAXP];

#define CP_ASYNC_4(dst, src) \
    asm volatile("cp.async.ca.shared.global [%0], [%1], 4;"  :: "r"(dst), "l"(src) : "memory")
#define CP_COMMIT()  asm volatile("cp.async.commit_group;" ::: "memory")
#define CP_WAIT0()   asm volatile("cp.async.wait_group 0;" ::: "memory")

#define MBAR_INIT(mbar, cnt) \
    asm volatile("mbarrier.init.shared.b64 [%0], %1;" :: "r"(mbar), "r"(cnt) : "memory")
#define MBAR_EXPECT_TX(mbar, bytes) \
    asm volatile("mbarrier.arrive.expect_tx.shared.b64 _, [%0], %1;" :: "r"(mbar), "r"(bytes) : "memory")
#define FENCE_PROXY_ASYNC() asm volatile("fence.proxy.async.shared::cta;" ::: "memory")

#define MBAR_WAIT(mbar, par) do {                                              \
    uint32_t _m = (mbar); uint32_t _p = (par); uint32_t _d;                    \
    asm volatile("{\n\t.reg .pred p;\n\t"                                      \
        "mbarrier.try_wait.parity.acquire.cta.shared::cta.b64 p, [%1], %2;\n\t"\
        "selp.b32 %0, 1, 0, p;\n\t}"                                           \
        : "=r"(_d) : "r"(_m), "r"(_p) : "memory");                             \
    if (!_d) {                                                                 \
        asm volatile("{\n\t.reg .pred P1;\n\t"                                 \
            "WL_%=:\n\t"                                                       \
            "mbarrier.try_wait.parity.acquire.cta.shared::cta.b64 P1, [%0], %1, 0x989680;\n\t" \
            "@P1 bra.uni WD_%=;\n\t"                                           \
            "bra.uni WL_%=;\n\t"                                               \
            "WD_%=:\n\t}"                                                      \
            :: "r"(_m), "r"(_p) : "memory");                                   \
    }                                                                          \
} while (0)

#define BULK_LD(dst, src, bytes, mbar) \
    asm volatile("cp.async.bulk.shared::cluster.global.mbarrier::complete_tx::bytes " \
                 "[%0], [%1], %2, [%3];" \
                 :: "r"(dst), "l"(src), "r"(bytes), "r"(mbar) : "memory")

static __device__ __forceinline__ uint32_t smem_u32(const void* p) {
    return (uint32_t)__cvta_generic_to_shared(p);
}

// Exact floor(r/41) for 0 <= r < 53773.
static __device__ __forceinline__ int div41(int r) {
    return (int)(((unsigned)r * 51151u) >> 21);
}

// ---------------------------------------------------------------------------
// One launch, grid = 2*NC: each CTA streams HALF a problem's rows (doubles
// resident CTAs/SM -> measured stream-BW lever), writes its rowmax half to a
// global table, then the SECOND CTA to finish (atomic ticket; replay-safe via
// odd/even old value) runs phase-2 NMS + epilogue with L2-hot data.
__global__ __launch_bounds__(THREADS, 7)
void split_peaks_kernel(const float* __restrict__ density,
                        const float* __restrict__ grid_xyz,
                        const float* __restrict__ Rmats,
                        const float* __restrict__ tpos,
                        const float* __restrict__ node_mask,
                        float* __restrict__ out,
                        int C)
{
    extern __shared__ char smem[];
    float*   bufs   = (float*)(smem + SM_BUF);
    uint8_t* rowlo  = (uint8_t*)(smem + SM_ROWLO);
    float*   xs2    = (float*)(smem + SM_XS2);
    float*   ys2    = (float*)(smem + SM_YS2);
    float*   zz     = (float*)(smem + SM_ZZ);
    float*   swv    = (float*)(smem + SM_SWV);
    int*     swr    = (int*)(smem + SM_SWR);
    int*     s_pick = (int*)(smem + SM_PICK);
    int*     s_pkk  = (int*)(smem + SM_PKK);
    float*   s_ps   = (float*)(smem + SM_PS);
    int*     s_pg   = (int*)(smem + SM_PG);
    int*     s_pv   = (int*)(smem + SM_PV);
    int*     s_flag = (int*)(smem + SM_FLAG);

    const int tid  = threadIdx.x;
    const int lane = tid & 31;
    const int w    = tid >> 5;
    const int q    = blockIdx.x;
    const int p    = q >> 1;
    const int h    = q & 1;
    const int NC   = (int)(gridDim.x >> 1);
    const int r0h    = h ? HALF0 : 0;
    const int nrowsH = h ? (NROWS - HALF0) : HALF0;
    const int nch    = (nrowsH + ACH - 1) / ACH;
    const size_t base    = (size_t)p * GVOX;
    const size_t total_f = (size_t)NC * GVOX;
    const uint32_t mb = smem_u32(smem + SM_MBAR);

    auto issue_chunk = [&](int c) -> bool {
        const int row0  = r0h + c * ACH;
        const int nrows = min(ACH, r0h + nrowsH - row0);
        const size_t need_start = base + (size_t)row0 * NXG;
        const size_t srcA = need_start & ~(size_t)3;
        size_t endA = (need_start + (size_t)nrows * NXG + 3) & ~(size_t)3;
        bool tail = false;
        if (endA > total_f) { endA -= 4; tail = true; }
        const uint32_t bytes = (uint32_t)(endA - srcA) * 4u;
        const int st = c % ANST;
        const uint32_t dstb = smem_u32(bufs + (size_t)st * ACHBUF);
        const uint32_t mbar = mb + (uint32_t)st * 8u;
        if (tid == 0) {
            MBAR_EXPECT_TX(mbar, bytes);
            BULK_LD(dstb, density + srcA, bytes, mbar);
        }
        if (tail) {
            const size_t need_end = need_start + (size_t)nrows * NXG;
            const int nrem = (int)(need_end - endA);          // 1..4
            if (tid < nrem)
                CP_ASYNC_4(dstb + (uint32_t)(endA - srcA + tid) * 4u,
                           density + endA + tid);
            CP_COMMIT();
        }
        return tail;
    };

    if (tid == 0) {
        #pragma unroll
        for (int s = 0; s < ANST; s++) MBAR_INIT(mb + s * 8u, 1);
        FENCE_PROXY_ASYNC();
    }
    __syncthreads();

    bool tails[ANST] = {false, false, false};
    #pragma unroll
    for (int pc = 0; pc < ANST - 1; pc++)
        if (pc < nch) tails[pc] = issue_chunk(pc);

    // Per-axis squared coords from the ACTUAL grid_xyz input.
    // Sphere test (s<=36.0f) is bit-equivalent to sqrtf(s)<=6.0f under RN.
    if (tid < NXG) {
        float x = grid_xyz[3 * (tid * NXG * NXG) + 0];
        float y = grid_xyz[3 * (tid * NXG) + 1];
        float z = grid_xyz[3 * tid + 2];
        xs2[tid] = __fmul_rn(x, x);
        ys2[tid] = __fmul_rn(y, y);
        zz[tid]  = __fmul_rn(z, z);
    }
    __syncthreads();

    // Per-row valid interval for THIS CTA's rows: ks = [klo, 40-klo],
    // klo = 20-d, d = max{d: fadd(t2, zz[20+d]) <= 36} (monotone -> binary).
    for (int rr = tid; rr < nrowsH; rr += THREADS) {
        const int r = r0h + rr;
        const int i = div41(r);
        const int j = r - i * NXG;
        const float t2 = __fadd_rn(xs2[i], ys2[j]);
        int d = -1;
        #pragma unroll
        for (int step = 16; step; step >>= 1) {
            int nd = d + step;
            if (nd <= 20 && __fadd_rn(t2, zz[20 + nd]) <= 36.0f) d = nd;
        }
        rowlo[rr] = (uint8_t)(20 - d);     // 21 when row entirely outside sphere
    }
    __syncthreads();

    // ---------------- Phase 1: 3-stage ring + quad-per-row max ---------------
    for (int c = 0; c < nch; c++) {
        const int st = c % ANST;
        MBAR_WAIT(mb + (uint32_t)st * 8u, (uint32_t)((c / ANST) & 1));
        if (tails[st]) { CP_WAIT0(); __syncthreads(); tails[st] = false; }

        const int row0  = r0h + c * ACH;
        const int nrows = min(ACH, r0h + nrowsH - row0);
        const int sft   = (int)((base + (size_t)row0 * NXG) & 3);
        const int lr    = tid >> 2;                  // 0..63 (>= nrows guarded)
        const int qq    = tid & 3;
        const int rloc  = min(lr, nrows - 1);
        const int r     = row0 + rloc;
        const int klo   = (int)rowlo[r - r0h];
        const int khi   = 40 - klo;
        const int kb    = qq * 11;                   // [0,10][11,21][22,32][33,43]
        const float* rowp = bufs + (size_t)st * ACHBUF + sft + rloc * NXG + kb;

        float best = NEGF;
        #pragma unroll
        for (int kk = 0; kk < 11; kk++) {
            const int k = kb + kk;                   // k 41..43 excluded (khi<=40)
            const float v = rowp[kk];                // in-bounds via ACHBUF slack
            if (k >= klo && k <= khi) best = fmaxf(best, v);
        }
        #pragma unroll
        for (int off = 1; off <= 2; off <<= 1)
            best = fmaxf(best, __shfl_xor_sync(0xffffffffu, best, off));
        if (qq == 0 && lr < nrows)
            g_rowmax[(size_t)p * RPITCH + r] = best;
        __syncthreads();   // stage st fully consumed before refill below

        if (c + ANST - 1 < nch)
            tails[(c + ANST - 1) % ANST] = issue_chunk(c + ANST - 1);
    }

    // ---------------- Ticket: second CTA of this problem runs phase 2 --------
    __threadfence();   // publish our rowmax half
    if (tid == 0) {
        const int old = atomicAdd(&g_ticket[p], 1);
        *s_flag = (old & 1);   // each launch adds exactly 2 -> odd = second
    }
    __syncthreads();
    if (*s_flag == 0) return;   // first-finisher exits; peer does phase 2
    __threadfence();            // peer's table writes visible (post-atomic)

    // Load full row table into the (now dead) ring buffer area.
    float* rowmax = bufs;
    for (int r = tid; r < NROWS; r += THREADS)
        rowmax[r] = g_rowmax[(size_t)p * RPITCH + r];
    __syncthreads();

    // ---------------- Phase 2: K iterations of argmax + local NMS ------------
    int pk_i[KP], pk_j[KP], pk_k[KP];
    int npk = 0;   // replicated across threads (derived from shared data)

    for (int it = 0; it < KP; it++) {
        // Block argmax over rowmax[0..1680], first-occurrence tie-break.
        float bv = -__int_as_float(0x7f800000);
        int   br = 0x7fffffff;
        for (int r = tid; r < NROWS; r += THREADS) {
            float v = rowmax[r];
            if (v > bv) { bv = v; br = r; }        // r ascending: ties keep earlier
        }
        #pragma unroll
        for (int off = 16; off; off >>= 1) {
            float ov = __shfl_xor_sync(0xffffffffu, bv, off);
            int   orr = __shfl_xor_sync(0xffffffffu, br, off);
            if (ov > bv || (ov == bv && orr < br)) { bv = ov; br = orr; }
        }
        if (lane == 0) { swv[w] = bv; swr[w] = br; }
        __syncthreads();
        if (w == 0) {
            float v = (lane < NWARP) ? swv[lane] : -__int_as_float(0x7f800000);
            int   r = (lane < NWARP) ? swr[lane] : 0x7fffffff;
            #pragma unroll
            for (int off = 4; off; off >>= 1) {
                float ov = __shfl_xor_sync(0xffffffffu, v, off);
                int   orr = __shfl_xor_sync(0xffffffffu, r, off);
                if (ov > v || (ov == v && orr < r)) { v = ov; r = orr; }
            }
            if (lane == 0) *s_pick = r;
        }
        __syncthreads();

        const int   pr  = *s_pick;
        const float sc  = rowmax[pr];
        const int   pi  = div41(pr);
        const int   pj  = pr - pi * NXG;
        const bool  valid = sc > VTH;

        // Warp 0 recomputes argmax-k of the picked row (mask + suppression by
        // the npk peaks picked so far; first-k tie-break). L2-hot loads.
        if (w == 0) {
            const float t2 = __fadd_rn(xs2[pi], ys2[pj]);
            const float* rowg = density + base + (size_t)pr * NXG;
            bool in0 = 0 < npk && abs(pi - pk_i[0]) <= SEP && abs(pj - pk_j[0]) <= SEP;
            bool in1 = 1 < npk && abs(pi - pk_i[1]) <= SEP && abs(pj - pk_j[1]) <= SEP;
            bool in2 = 2 < npk && abs(pi - pk_i[2]) <= SEP && abs(pj - pk_j[2]) <= SEP;

            float bvv = NEGF; int bkk = lane;
            {
                const int k = lane;
                bool sup = (__fadd_rn(t2, zz[k]) > 36.0f);
                if (in0 && abs(k - pk_k[0]) <= SEP) sup = true;
                if (in1 && abs(k - pk_k[1]) <= SEP) sup = true;
                if (in2 && abs(k - pk_k[2]) <= SEP) sup = true;
                if (!sup) bvv = __ldg(&rowg[k]);
            }
            const int k2 = lane + 32;
            if (k2 < NXG) {
                bool sup = (__fadd_rn(t2, zz[k2]) > 36.0f);
                if (in0 && abs(k2 - pk_k[0]) <= SEP) sup = true;
                if (in1 && abs(k2 - pk_k[1]) <= SEP) sup = true;
                if (in2 && abs(k2 - pk_k[2]) <= SEP) sup = true;
                if (!sup) {
                    const float v2 = __ldg(&rowg[k2]);
                    if (v2 > bvv) { bvv = v2; bkk = k2; }
                }
            }
            #pragma unroll
            for (int off = 16; off; off >>= 1) {
                const float ov = __shfl_xor_sync(0xffffffffu, bvv, off);
                const int   ok = __shfl_xor_sync(0xffffffffu, bkk, off);
                if (ov > bvv || (ov == bvv && ok < bkk)) { bvv = ov; bkk = ok; }
            }
            if (lane == 0) *s_pkk = bkk;
        }
        __syncthreads();

        const int pkk = *s_pkk;
        if (tid == 0) {
            s_ps[it] = sc;
            s_pg[it] = pr * NXG + pkk;
            s_pv[it] = valid ? 1 : 0;
        }
        if (valid) { pk_i[npk] = pi; pk_j[npk] = pj; pk_k[npk] = pkk; npk++; }
        __syncthreads();   // everyone done reading rowmax before rewrite

        if (it == KP - 1) break;

        // Recompute rows intersecting the new peak's Chebyshev ball, applying
        // suppression from ALL picked-so-far peaks. Max value only.
        if (valid) {
            const int i0 = max(pi - SEP, 0), i1 = min(pi + SEP, NXG - 1);
            const int j0 = max(pj - SEP, 0), j1 = min(pj + SEP, NXG - 1);
            const int nj = j1 - j0 + 1;
            const int nr = (i1 - i0 + 1) * nj;
            if (tid < nr) {
                const int i = i0 + tid / nj;
                const int j = j0 + tid % nj;
                const int r = i * NXG + j;
                const float t2 = __fadd_rn(xs2[i], ys2[j]);
                const float* rowg = density + base + (size_t)r * NXG;

                bool in0 = 0 < npk && abs(i - pk_i[0]) <= SEP && abs(j - pk_j[0]) <= SEP;
                bool in1 = 1 < npk && abs(i - pk_i[1]) <= SEP && abs(j - pk_j[1]) <= SEP;
                bool in2 = 2 < npk && abs(i - pk_i[2]) <= SEP && abs(j - pk_j[2]) <= SEP;

                float best = NEGF;
                #pragma unroll
                for (int k = 0; k < NXG; k++) {
                    const float dv = __ldg(&rowg[k]);   // unconditional: enables MLP
                    bool sup = (__fadd_rn(t2, zz[k]) > 36.0f);
                    if (in0 && abs(k - pk_k[0]) <= SEP) sup = true;
                    if (in1 && abs(k - pk_k[1]) <= SEP) sup = true;
                    if (in2 && abs(k - pk_k[2]) <= SEP) sup = true;
                    best = fmaxf(best, sup ? NEGF : dv);
                }
                rowmax[r] = best;
            }
        }
        __syncthreads();
    }

    // ---------------- Epilogue: transform + write outputs --------------------
    // Output layout: coords_local [NC,K,3] | coords_global [NC,K,3] |
    //                scores [NC,K] | mask [NC,K]  (all float32)
    if (tid < KP) {
        const int kk = tid;
        const int n  = p / C;

        const float sc    = s_ps[kk];
        const bool  valid = (s_pv[kk] != 0);
        const int   g     = s_pg[kk];

        float x = 0.f, y = 0.f, z = 0.f;
        if (valid) {
            x = grid_xyz[3 * g + 0];
            y = grid_xyz[3 * g + 1];
            z = grid_xyz[3 * g + 2];
        }
        const float nm = node_mask[n];
        const float* R = Rmats + (size_t)n * 9;
        const float* t = tpos  + (size_t)n * 3;
        const float gx = R[0] * x + R[1] * y + R[2] * z + t[0];
        const float gy = R[3] * x + R[4] * y + R[5] * z + t[1];
        const float gz = R[6] * x + R[7] * y + R[8] * z + t[2];

        float* CL = out;
        float* CG = out + (size_t)NC * KP * 3;
        float* SC = out + (size_t)NC * KP * 6;
        float* MS = SC  + (size_t)NC * KP;

        const size_t o3 = ((size_t)p * KP + kk) * 3;
        CL[o3 + 0] = x * nm;  CL[o3 + 1] = y * nm;  CL[o3 + 2] = z * nm;
        CG[o3 + 0] = gx * nm; CG[o3 + 1] = gy * nm; CG[o3 + 2] = gz * nm;
        SC[(size_t)p * KP + kk] = (valid ? sc : NEGF) * nm;
        MS[(size_t)p * KP + kk] = (valid && nm != 0.0f) ? 1.0f : 0.0f;
    }
}

extern "C" void kernel_launch(void* const* d_in, const int* in_sizes, int n_in,
                              void* d_out, int out_size)
{
    // Input order per reference setup_inputs():
    // 0: density [B,N,C,G] f32   1: grid_xyz [G,3] f32   2: sphere_mask (unused)
    // 3: coords_int (unused)     4: Rmats [B,N,3,3] f32  5: tpos [B,N,3] f32
    // 6: node_mask [B,N] f32
    const float* density   = (const float*)d_in[0];
    const float* grid_xyz  = (const float*)d_in[1];
    const float* Rmats     = (const float*)d_in[4];
    const float* tposp     = (const float*)d_in[5];
    const float* node_mask = (const float*)d_in[6];
    float* out = (float*)d_out;

    const int NC = in_sizes[0] / GVOX;      // B*N*C = 512
    const int N  = in_sizes[4] / 9;         // B*N   = 128
    const int C  = NC / N;                  // 4
    (void)n_in; (void)out_size;

    static int smem_set = 0;
    if (!smem_set) {
        cudaFuncSetAttribute(split_peaks_kernel,
                             cudaFuncAttributeMaxDynamicSharedMemorySize, SM_TOTAL);
        smem_set = 1;
    }
    split_peaks_kernel<<<2 * NC, THREADS, SM_TOTAL>>>(density, grid_xyz, Rmats,
                                                      tposp, node_mask, out, C);
}

// round 14
// speedup vs baseline: 1.1531x; 1.1531x over previous
#include <cuda_runtime.h>
#include <stdint.h>

// Problem constants (fixed by the reference: NX=41, r_max=6.0, voxel=0.3, K=4, min_sep=3)
#define NXG    41
#define NROWS  (NXG * NXG)       // 1681 rows of 41 voxels
#define GVOX   (NXG * NXG * NXG) // 68921
#define KP     4
#define SEP    3
#define NEGF   (-1.0e9f)
#define VTH    (-1.0e8f)

#define THREADS 256
#define NWARP   8
#define NSTAGE  2
#define CHROWS  128                             // rows per block chunk
#define TMAROWS 64                              // first 64 rows via TMA bulk
#define LDGROWS (CHROWS - TMAROWS)              // last 64 rows via LDG->STS
#define LDGCNT  (LDGROWS * NXG)                 // 2624 floats
#define NCHUNK  ((NROWS + CHROWS - 1) / CHROWS) // 14
#define CHBUF   (CHROWS * NXG + 8)              // 5256 floats = 21024 B (mult of 16)

// Shared-memory layout (bytes); buffers 16B-aligned.
#define SM_BUF    0                                   // 2 * 21024 = 42048
#define SM_MBAR   (SM_BUF + 2 * CHBUF * 4)            // 16
#define SM_ROWMAX (SM_MBAR + 16)                      // 6724
#define SM_ROWLO  (SM_ROWMAX + NROWS * 4)             // 1684
#define SM_XS2    (SM_ROWLO + 1684)                   // 168
#define SM_YS2    (SM_XS2 + 168)
#define SM_ZZ     (SM_YS2 + 168)
#define SM_SWV    (SM_ZZ + 168)
#define SM_SWR    (SM_SWV + 32)
#define SM_PICK   (SM_SWR + 32)
#define SM_PKK    (SM_PICK + 4)
#define SM_PS     (SM_PKK + 4)
#define SM_PG     (SM_PS + 16)
#define SM_PV     (SM_PG + 16)
#define SM_TOTAL  (SM_PV + 16 + 32)                   // ~51.2 KB -> 4 CTAs/SM

#define CP_ASYNC_4(dst, src) \
    asm volatile("cp.async.ca.shared.global [%0], [%1], 4;"  :: "r"(dst), "l"(src) : "memory")
#define CP_COMMIT()  asm volatile("cp.async.commit_group;" ::: "memory")
#define CP_WAIT0()   asm volatile("cp.async.wait_group 0;" ::: "memory")

#define MBAR_INIT(mbar, cnt) \
    asm volatile("mbarrier.init.shared.b64 [%0], %1;" :: "r"(mbar), "r"(cnt) : "memory")
#define MBAR_EXPECT_TX(mbar, bytes) \
    asm volatile("mbarrier.arrive.expect_tx.shared.b64 _, [%0], %1;" :: "r"(mbar), "r"(bytes) : "memory")
#define FENCE_PROXY_ASYNC() asm volatile("fence.proxy.async.shared::cta;" ::: "memory")

#define MBAR_WAIT(mbar, par) do {                                              \
    uint32_t _m = (mbar); uint32_t _p = (par); uint32_t _d;                    \
    asm volatile("{\n\t.reg .pred p;\n\t"                                      \
        "mbarrier.try_wait.parity.acquire.cta.shared::cta.b64 p, [%1], %2;\n\t"\
        "selp.b32 %0, 1, 0, p;\n\t}"                                           \
        : "=r"(_d) : "r"(_m), "r"(_p) : "memory");                             \
    if (!_d) {                                                                 \
        asm volatile("{\n\t.reg .pred P1;\n\t"                                 \
            "WL_%=:\n\t"                                                       \
            "mbarrier.try_wait.parity.acquire.cta.shared::cta.b64 P1, [%0], %1, 0x989680;\n\t" \
            "@P1 bra.uni WD_%=;\n\t"                                           \
            "bra.uni WL_%=;\n\t"                                               \
            "WD_%=:\n\t}"                                                      \
            :: "r"(_m), "r"(_p) : "memory");                                   \
    }                                                                          \
} while (0)

#define BULK_LD(dst, src, bytes, mbar) \
    asm volatile("cp.async.bulk.shared::cluster.global.mbarrier::complete_tx::bytes " \
                 "[%0], [%1], %2, [%3];" \
                 :: "r"(dst), "l"(src), "r"(bytes), "r"(mbar) : "memory")

static __device__ __forceinline__ uint32_t smem_u32(const void* p) {
    return (uint32_t)__cvta_generic_to_shared(p);
}

// Exact floor(r/41) for 0 <= r < 53773.
static __device__ __forceinline__ int div41(int r) {
    return (int)(((unsigned)r * 51151u) >> 21);
}

// ---------------------------------------------------------------------------
// Fully fused (R9 base = best known), with DUAL-PATH chunk ingest: rows 0..63
// of each 128-row chunk arrive via cp.async.bulk (TMA/async SMEM port), rows
// 64..127 via coalesced LDG->STS (LSU/ST port). If the two SMEM-ingest paths
// are independent, phase-1 bandwidth ~doubles past the measured 3.1TB/s cap.
__global__ __launch_bounds__(THREADS, 4)
void fused_peaks_kernel(const float* __restrict__ density,
                        const float* __restrict__ grid_xyz,
                        const float* __restrict__ Rmats,
                        const float* __restrict__ tpos,
                        const float* __restrict__ node_mask,
                        float* __restrict__ out,
                        int C)
{
    extern __shared__ char smem[];
    float*   buf0   = (float*)(smem + SM_BUF);
    float*   buf1   = buf0 + CHBUF;
    float*   rowmax = (float*)(smem + SM_ROWMAX);
    uint8_t* rowlo  = (uint8_t*)(smem + SM_ROWLO);
    float*   xs2    = (float*)(smem + SM_XS2);
    float*   ys2    = (float*)(smem + SM_YS2);
    float*   zz     = (float*)(smem + SM_ZZ);
    float*   swv    = (float*)(smem + SM_SWV);
    int*     swr    = (int*)(smem + SM_SWR);
    int*     s_pick = (int*)(smem + SM_PICK);
    int*     s_pkk  = (int*)(smem + SM_PKK);
    float*   s_ps   = (float*)(smem + SM_PS);
    int*     s_pg   = (int*)(smem + SM_PG);
    int*     s_pv   = (int*)(smem + SM_PV);

    const int tid  = threadIdx.x;
    const int lane = tid & 31;
    const int w    = tid >> 5;
    const int p    = blockIdx.x;
    const size_t base    = (size_t)p * GVOX;        // base % 4 == p % 4
    const size_t total_f = (size_t)gridDim.x * GVOX;
    const uint32_t mb = smem_u32(smem + SM_MBAR);
    const int sft = (int)(base & 3);                // same every chunk (CHROWS*NXG%4==0)

    // TMA half of chunk c: rows [row0, row0+min(TMAROWS,nrows)).
    auto issue_tma = [&](int c) -> bool {
        const int row0   = c * CHROWS;
        const int nrows  = min(CHROWS, NROWS - row0);
        const int trows  = min(TMAROWS, nrows);
        const size_t need_start = base + (size_t)row0 * NXG;
        const size_t srcA = need_start & ~(size_t)3;          // 16B-aligned float idx
        size_t endA = (need_start + (size_t)trows * NXG + 3) & ~(size_t)3;
        bool tail = false;
        if (endA > total_f) { endA -= 4; tail = true; }       // never when NC%4==0
        const uint32_t bytes = (uint32_t)(endA - srcA) * 4u;
        const uint32_t dstb  = smem_u32((c & 1) ? buf1 : buf0);
        const uint32_t mbar  = mb + (uint32_t)(c & 1) * 8u;
        if (tid == 0) {
            MBAR_EXPECT_TX(mbar, bytes);
            BULK_LD(dstb, density + srcA, bytes, mbar);
        }
        if (tail) {
            const size_t need_end = need_start + (size_t)trows * NXG;
            const int nrem = (int)(need_end - endA);          // 1..4
            if (tid < nrem)
                CP_ASYNC_4(dstb + (uint32_t)(endA - srcA + tid) * 4u,
                           density + endA + tid);
            CP_COMMIT();
        }
        return tail;
    };

    // LDG->STS half of chunk c: rows [row0+TMAROWS, row0+nrows).
    auto ldg_fill = [&](int c) {
        const int row0  = c * CHROWS;
        const int nrows = min(CHROWS, NROWS - row0);
        const int cnt   = max(0, nrows - TMAROWS) * NXG;      // 0 or 2624
        if (cnt == 0) return;
        const float* gsrc = density + base + (size_t)(row0 + TMAROWS) * NXG;
        float* sdst = ((c & 1) ? buf1 : buf0) + sft + TMAROWS * NXG;
        #pragma unroll
        for (int it = 0; it < 11; it++) {
            const int idx = tid + it * THREADS;
            if (idx < cnt) sdst[idx] = __ldg(&gsrc[idx]);
        }
    };

    if (tid == 0) {
        MBAR_INIT(mb, 1);
        MBAR_INIT(mb + 8, 1);
        FENCE_PROXY_ASYNC();
    }
    __syncthreads();          // mbarriers initialized before anyone waits

    bool tail_cur = issue_tma(0);
    ldg_fill(0);

    // Per-axis squared coords from the ACTUAL grid_xyz input.
    // Sphere test (s<=36.0f) is bit-equivalent to sqrtf(s)<=6.0f under RN.
    if (tid < NXG) {
        float x = grid_xyz[3 * (tid * NXG * NXG) + 0];
        float y = grid_xyz[3 * (tid * NXG) + 1];
        float z = grid_xyz[3 * tid + 2];
        xs2[tid] = __fmul_rn(x, x);
        ys2[tid] = __fmul_rn(y, y);
        zz[tid]  = __fmul_rn(z, z);
    }
    __syncthreads();

    // Per-row valid interval: valid ks = [klo, 40-klo], klo = 20-d where
    // d = max{d: fadd(t2, zz[20+d]) <= 36} (monotone predicate -> binary ascent;
    // zz exactly symmetric about 20 since (-x)*(-x)==x*x).
    for (int r = tid; r < NROWS; r += THREADS) {
        const int i = div41(r);
        const int j = r - i * NXG;
        const float t2 = __fadd_rn(xs2[i], ys2[j]);
        int d = -1;
        #pragma unroll
        for (int step = 16; step; step >>= 1) {
            int nd = d + step;
            if (nd <= 20 && __fadd_rn(t2, zz[20 + nd]) <= 36.0f) d = nd;
        }
        rowlo[r] = (uint8_t)(20 - d);      // 21 when row entirely outside sphere
    }
    __syncthreads();

    // ---------------- Phase 1: dual-path double-buffered chunks + row max ----
    for (int c = 0; c < NCHUNK; c++) {
        bool tail_next = false;
        if (c + 1 < NCHUNK) {
            tail_next = issue_tma(c + 1);
            ldg_fill(c + 1);               // LSU path overlaps TMA delivery
        }

        // Wait TMA half of chunk c; barrier also publishes the STS half.
        MBAR_WAIT(mb + (uint32_t)(c & 1) * 8u, (uint32_t)((c >> 1) & 1));
        if (tail_cur) CP_WAIT0();
        tail_cur = tail_next;
        __syncthreads();                   // orders STS(c) writes for all readers

        // Pair-per-row: even tid ks [0,21), odd [21,41). MAX ONLY.
        const int row0  = c * CHROWS;
        const int nrows = min(CHROWS, NROWS - row0);
        const int lr    = tid >> 1;                  // 0..127
        const int half  = tid & 1;
        const int r     = min(row0 + lr, NROWS - 1);
        const int klo   = (int)rowlo[r];
        const int khi   = 40 - klo;
        const int kb    = half * 21;
        const float* rowp = ((c & 1) ? buf1 : buf0) + sft + lr * NXG + kb;

        float best = NEGF;
        #pragma unroll
        for (int kk = 0; kk < 21; kk++) {
            const int k = kb + kk;                   // k=41 slot: khi<41 -> invalid
            const float v = rowp[kk];                // in-bounds via CHBUF slack
            if (k >= klo && k <= khi) best = fmaxf(best, v);
        }
        const float vo = __shfl_down_sync(0xffffffffu, best, 1);
        if (half == 0 && lr < nrows)
            rowmax[row0 + lr] = fmaxf(best, vo);
        __syncthreads();   // all threads done with buffer (c&1) before refill
    }

    // ---------------- Phase 2: K iterations of argmax + local NMS ------------
    int pk_i[KP], pk_j[KP], pk_k[KP];
    int npk = 0;   // replicated across threads (derived from shared data)

    for (int it = 0; it < KP; it++) {
        // Block argmax over rowmax[0..1680], first-occurrence tie-break.
        float bv = -__int_as_float(0x7f800000);
        int   br = 0x7fffffff;
        for (int r = tid; r < NROWS; r += THREADS) {
            float v = rowmax[r];
            if (v > bv) { bv = v; br = r; }        // r ascending: ties keep earlier
        }
        #pragma unroll
        for (int off = 16; off; off >>= 1) {
            float ov = __shfl_xor_sync(0xffffffffu, bv, off);
            int   orr = __shfl_xor_sync(0xffffffffu, br, off);
            if (ov > bv || (ov == bv && orr < br)) { bv = ov; br = orr; }
        }
        if (lane == 0) { swv[w] = bv; swr[w] = br; }
        __syncthreads();
        if (w == 0) {
            float v = (lane < NWARP) ? swv[lane] : -__int_as_float(0x7f800000);
            int   r = (lane < NWARP) ? swr[lane] : 0x7fffffff;
            #pragma unroll
            for (int off = 4; off; off >>= 1) {
                float ov = __shfl_xor_sync(0xffffffffu, v, off);
                int   orr = __shfl_xor_sync(0xffffffffu, r, off);
                if (ov > v || (ov == v && orr < r)) { v = ov; r = orr; }
            }
            if (lane == 0) *s_pick = r;
        }
        __syncthreads();

        const int   pr  = *s_pick;
        const float sc  = rowmax[pr];
        const int   pi  = div41(pr);
        const int   pj  = pr - pi * NXG;
        const bool  valid = sc > VTH;

        // Warp 0 recomputes argmax-k of the picked row (mask + suppression by
        // the npk peaks picked so far; first-k tie-break). L2-hot loads.
        if (w == 0) {
            const float t2 = __fadd_rn(xs2[pi], ys2[pj]);
            const float* rowg = density + base + (size_t)pr * NXG;
            bool in0 = 0 < npk && abs(pi - pk_i[0]) <= SEP && abs(pj - pk_j[0]) <= SEP;
            bool in1 = 1 < npk && abs(pi - pk_i[1]) <= SEP && abs(pj - pk_j[1]) <= SEP;
            bool in2 = 2 < npk && abs(pi - pk_i[2]) <= SEP && abs(pj - pk_j[2]) <= SEP;

            float bvv = NEGF; int bkk = lane;
            {
                const int k = lane;
                bool sup = (__fadd_rn(t2, zz[k]) > 36.0f);
                if (in0 && abs(k - pk_k[0]) <= SEP) sup = true;
                if (in1 && abs(k - pk_k[1]) <= SEP) sup = true;
                if (in2 && abs(k - pk_k[2]) <= SEP) sup = true;
                if (!sup) bvv = __ldg(&rowg[k]);
            }
            const int k2 = lane + 32;
            if (k2 < NXG) {
                bool sup = (__fadd_rn(t2, zz[k2]) > 36.0f);
                if (in0 && abs(k2 - pk_k[0]) <= SEP) sup = true;
                if (in1 && abs(k2 - pk_k[1]) <= SEP) sup = true;
                if (in2 && abs(k2 - pk_k[2]) <= SEP) sup = true;
                if (!sup) {
                    const float v2 = __ldg(&rowg[k2]);
                    if (v2 > bvv) { bvv = v2; bkk = k2; }
                }
            }
            #pragma unroll
            for (int off = 16; off; off >>= 1) {
                const float ov = __shfl_xor_sync(0xffffffffu, bvv, off);
                const int   ok = __shfl_xor_sync(0xffffffffu, bkk, off);
                if (ov > bvv || (ov == bvv && ok < bkk)) { bvv = ov; bkk = ok; }
            }
            if (lane == 0) *s_pkk = bkk;
        }
        __syncthreads();

        const int pkk = *s_pkk;
        if (tid == 0) {
            s_ps[it] = sc;
            s_pg[it] = pr * NXG + pkk;
            s_pv[it] = valid ? 1 : 0;
        }
        if (valid) { pk_i[npk] = pi; pk_j[npk] = pj; pk_k[npk] = pkk; npk++; }
        __syncthreads();   // everyone done reading rowmax before rewrite

        if (it == KP - 1) break;

        // Recompute rows intersecting the new peak's Chebyshev ball, applying
        // suppression from ALL picked-so-far peaks. Max value only.
        if (valid) {
            const int i0 = max(pi - SEP, 0), i1 = min(pi + SEP, NXG - 1);
            const int j0 = max(pj - SEP, 0), j1 = min(pj + SEP, NXG - 1);
            const int nj = j1 - j0 + 1;
            const int nr = (i1 - i0 + 1) * nj;
            if (tid < nr) {
                const int i = i0 + tid / nj;
                const int j = j0 + tid % nj;
                const int r = i * NXG + j;
                const float t2 = __fadd_rn(xs2[i], ys2[j]);
                const float* rowg = density + base + (size_t)r * NXG;

                bool in0 = 0 < npk && abs(i - pk_i[0]) <= SEP && abs(j - pk_j[0]) <= SEP;
                bool in1 = 1 < npk && abs(i - pk_i[1]) <= SEP && abs(j - pk_j[1]) <= SEP;
                bool in2 = 2 < npk && abs(i - pk_i[2]) <= SEP && abs(j - pk_j[2]) <= SEP;

                float best = NEGF;
                #pragma unroll
                for (int k = 0; k < NXG; k++) {
                    const float dv = __ldg(&rowg[k]);   // unconditional: enables MLP
                    bool sup = (__fadd_rn(t2, zz[k]) > 36.0f);
                    if (in0 && abs(k - pk_k[0]) <= SEP) sup = true;
                    if (in1 && abs(k - pk_k[1]) <= SEP) sup = true;
                    if (in2 && abs(k - pk_k[2]) <= SEP) sup = true;
                    best = fmaxf(best, sup ? NEGF : dv);
                }
                rowmax[r] = best;
            }
        }
        __syncthreads();
    }

    // ---------------- Epilogue: transform + write outputs --------------------
    // Output layout: coords_local [NC,K,3] | coords_global [NC,K,3] |
    //                scores [NC,K] | mask [NC,K]  (all float32)
    if (tid < KP) {
        const int kk = tid;
        const int n  = p / C;
        const int NC = gridDim.x;

        const float sc    = s_ps[kk];
        const bool  valid = (s_pv[kk] != 0);
        const int   g     = s_pg[kk];

        float x = 0.f, y = 0.f, z = 0.f;
        if (valid) {
            x = grid_xyz[3 * g + 0];
            y = grid_xyz[3 * g + 1];
            z = grid_xyz[3 * g + 2];
        }
        const float nm = node_mask[n];
        const float* R = Rmats + (size_t)n * 9;
        const float* t = tpos  + (size_t)n * 3;
        const float gx = R[0] * x + R[1] * y + R[2] * z + t[0];
        const float gy = R[3] * x + R[4] * y + R[5] * z + t[1];
        const float gz = R[6] * x + R[7] * y + R[8] * z + t[2];

        float* CL = out;
        float* CG = out + (size_t)NC * KP * 3;
        float* SC = out + (size_t)NC * KP * 6;
        float* MS = SC  + (size_t)NC * KP;

        const size_t o3 = ((size_t)p * KP + kk) * 3;
        CL[o3 + 0] = x * nm;  CL[o3 + 1] = y * nm;  CL[o3 + 2] = z * nm;
        CG[o3 + 0] = gx * nm; CG[o3 + 1] = gy * nm; CG[o3 + 2] = gz * nm;
        SC[(size_t)p * KP + kk] = (valid ? sc : NEGF) * nm;
        MS[(size_t)p * KP + kk] = (valid && nm != 0.0f) ? 1.0f : 0.0f;
    }
}

extern "C" void kernel_launch(void* const* d_in, const int* in_sizes, int n_in,
                              void* d_out, int out_size)
{
    // Input order per reference setup_inputs():
    // 0: density [B,N,C,G] f32   1: grid_xyz [G,3] f32   2: sphere_mask (unused)
    // 3: coords_int (unused)     4: Rmats [B,N,3,3] f32  5: tpos [B,N,3] f32
    // 6: node_mask [B,N] f32
    const float* density   = (const float*)d_in[0];
    const float* grid_xyz  = (const float*)d_in[1];
    const float* Rmats     = (const float*)d_in[4];
    const float* tposp     = (const float*)d_in[5];
    const float* node_mask = (const float*)d_in[6];
    float* out = (float*)d_out;

    const int NC = in_sizes[0] / GVOX;      // B*N*C = 512
    const int N  = in_sizes[4] / 9;         // B*N   = 128
    const int C  = NC / N;                  // 4
    (void)n_in; (void)out_size;

    static int smem_set = 0;
    if (!smem_set) {
        cudaFuncSetAttribute(fused_peaks_kernel,
                             cudaFuncAttributeMaxDynamicSharedMemorySize, SM_TOTAL);
        smem_set = 1;
    }
    fused_peaks_kernel<<<NC, THREADS, SM_TOTAL>>>(density, grid_xyz, Rmats, tposp,
                                                  node_mask, out, C);
}

// round 15
// speedup vs baseline: 1.3117x; 1.1375x over previous
#include <cuda_runtime.h>
#include <stdint.h>

// Problem constants (fixed by the reference: NX=41, r_max=6.0, voxel=0.3, K=4, min_sep=3)
#define NXG    41
#define NROWS  (NXG * NXG)       // 1681 rows of 41 voxels
#define GVOX   (NXG * NXG * NXG) // 68921
#define KP     4
#define SEP    3
#define NEGF   (-1.0e9f)
#define VTH    (-1.0e8f)

#define THREADS 256
#define NWARP   8
#define NST     3                 // ring stages
#define NCK     21                // chunks: 2 slabs each (last has 1)
#define SLABBUF 1688              // floats per slab slot (41*41=1681 + slack; 6752B, %16==0)
#define STAGEF  (2 * SLABBUF)     // floats per stage (2 slab slots)

// Shared-memory layout (bytes)
#define SM_BUF    0                                   // 3 * 3376 * 4 = 40512
#define SM_MBAR   40512                               // 3 mbarriers (pad to 40544)
#define SM_ROWMAX 40544                               // 6724
#define SM_ROWLO  47268                               // 1684
#define SM_DJ     48952                               // 41 int8 (pad 44)
#define SM_XS2    48996                               // 168
#define SM_YS2    49164
#define SM_ZZ     49332
#define SM_SWV    49500                               // 32
#define SM_SWR    49532                               // 32
#define SM_PICK   49564
#define SM_PKK    49568
#define SM_PS     49572                               // 16
#define SM_PG     49588                               // 16
#define SM_PV     49604                               // 16
#define SM_TOTAL  49632                               // ~48.5KB -> 4 CTAs/SM

#define MBAR_INIT(mbar, cnt) \
    asm volatile("mbarrier.init.shared.b64 [%0], %1;" :: "r"(mbar), "r"(cnt) : "memory")
#define MBAR_EXPECT_TX(mbar, bytes) \
    asm volatile("mbarrier.arrive.expect_tx.shared.b64 _, [%0], %1;" :: "r"(mbar), "r"(bytes) : "memory")
#define FENCE_PROXY_ASYNC() asm volatile("fence.proxy.async.shared::cta;" ::: "memory")

#define MBAR_WAIT(mbar, par) do {                                              \
    uint32_t _m = (mbar); uint32_t _p = (par); uint32_t _d;                    \
    asm volatile("{\n\t.reg .pred p;\n\t"                                      \
        "mbarrier.try_wait.parity.acquire.cta.shared::cta.b64 p, [%1], %2;\n\t"\
        "selp.b32 %0, 1, 0, p;\n\t}"                                           \
        : "=r"(_d) : "r"(_m), "r"(_p) : "memory");                             \
    if (!_d) {                                                                 \
        asm volatile("{\n\t.reg .pred P1;\n\t"                                 \
            "WL_%=:\n\t"                                                       \
            "mbarrier.try_wait.parity.acquire.cta.shared::cta.b64 P1, [%0], %1, 0x989680;\n\t" \
            "@P1 bra.uni WD_%=;\n\t"                                           \
            "bra.uni WL_%=;\n\t"                                               \
            "WD_%=:\n\t}"                                                      \
            :: "r"(_m), "r"(_p) : "memory");                                   \
    }                                                                          \
} while (0)

#define BULK_LD(dst, src, bytes, mbar) \
    asm volatile("cp.async.bulk.shared::cluster.global.mbarrier::complete_tx::bytes " \
                 "[%0], [%1], %2, [%3];" \
                 :: "r"(dst), "l"(src), "r"(bytes), "r"(mbar) : "memory")

static __device__ __forceinline__ uint32_t smem_u32(const void* p) {
    return (uint32_t)__cvta_generic_to_shared(p);
}

// Exact floor(r/41) for 0 <= r < 53773.
static __device__ __forceinline__ int div41(int r) {
    return (int)(((unsigned)r * 51151u) >> 21);
}

// ---------------------------------------------------------------------------
// Fully fused, SPHERE-AWARE streaming: per i-slab, only the contiguous valid-j
// band [20-dj, 20+dj] is loaded (skips the 25% of rows entirely outside the
// sphere -> 141MB -> ~106MB against the measured ~3.1TB/s staging cap).
// 3-stage ring, 2 slabs per stage (2 bulk copies -> one mbarrier). Phase-1 is
// max-only; picked-row argmax-k recomputed in phase 2 (L2-hot).
__global__ __launch_bounds__(THREADS, 4)
void fused_peaks_kernel(const float* __restrict__ density,
                        const float* __restrict__ grid_xyz,
                        const float* __restrict__ Rmats,
                        const float* __restrict__ tpos,
                        const float* __restrict__ node_mask,
                        float* __restrict__ out,
                        int C)
{
    extern __shared__ char smem[];
    float*   bufs   = (float*)(smem + SM_BUF);
    float*   rowmax = (float*)(smem + SM_ROWMAX);
    uint8_t* rowlo  = (uint8_t*)(smem + SM_ROWLO);
    int8_t*  djt    = (int8_t*)(smem + SM_DJ);
    float*   xs2    = (float*)(smem + SM_XS2);
    float*   ys2    = (float*)(smem + SM_YS2);
    float*   zz     = (float*)(smem + SM_ZZ);
    float*   swv    = (float*)(smem + SM_SWV);
    int*     swr    = (int*)(smem + SM_SWR);
    int*     s_pick = (int*)(smem + SM_PICK);
    int*     s_pkk  = (int*)(smem + SM_PKK);
    float*   s_ps   = (float*)(smem + SM_PS);
    int*     s_pg   = (int*)(smem + SM_PG);
    int*     s_pv   = (int*)(smem + SM_PV);

    const int tid  = threadIdx.x;
    const int lane = tid & 31;
    const int w    = tid >> 5;
    const int p    = blockIdx.x;
    const size_t base = (size_t)p * GVOX;           // base % 4 == p % 4
    const uint32_t mb = smem_u32(smem + SM_MBAR);

    // Issue chunk ci: slabs 2ci and 2ci+1, each a single bulk copy of its
    // valid-row band; one mbarrier accumulates both deliveries.
    auto issue_chunk = [&](int ci) {
        if (tid != 0) return;
        const int st2 = ci % NST;
        const uint32_t mbar = mb + (uint32_t)st2 * 8u;
        const uint32_t dstb = smem_u32(bufs + (size_t)st2 * STAGEF);
        uint32_t b0 = 0, b1 = 0; size_t src0 = 0, src1 = 0;
        const int s0 = 2 * ci, s1v = 2 * ci + 1;
        const int d0 = (int)djt[s0];
        if (d0 >= 0) {
            const size_t stt = base + (size_t)(s0 * NXG + (20 - d0)) * NXG;
            const size_t sA = stt & ~(size_t)3;
            const size_t eA = (stt + (size_t)(2 * d0 + 1) * NXG + 3) & ~(size_t)3;
            src0 = sA; b0 = (uint32_t)(eA - sA) * 4u;   // never past array end
        }
        if (s1v <= 40) {
            const int d1 = (int)djt[s1v];
            if (d1 >= 0) {
                const size_t stt = base + (size_t)(s1v * NXG + (20 - d1)) * NXG;
                const size_t sA = stt & ~(size_t)3;
                const size_t eA = (stt + (size_t)(2 * d1 + 1) * NXG + 3) & ~(size_t)3;
                src1 = sA; b1 = (uint32_t)(eA - sA) * 4u;
            }
        }
        MBAR_EXPECT_TX(mbar, b0 + b1);   // b==0 case: arrive alone completes
        if (b0) BULK_LD(dstb, density + src0, b0, mbar);
        if (b1) BULK_LD(dstb + (uint32_t)SLABBUF * 4u, density + src1, b1, mbar);
    };

    if (tid == 0) {
        #pragma unroll
        for (int s = 0; s < NST; s++) MBAR_INIT(mb + s * 8u, 1);
        FENCE_PROXY_ASYNC();
    }

    // Per-axis squared coords from the ACTUAL grid_xyz input.
    // Sphere test (s<=36.0f) is bit-equivalent to sqrtf(s)<=6.0f under RN.
    if (tid < NXG) {
        float x = grid_xyz[3 * (tid * NXG * NXG) + 0];
        float y = grid_xyz[3 * (tid * NXG) + 1];
        float z = grid_xyz[3 * tid + 2];
        xs2[tid] = __fmul_rn(x, x);
        ys2[tid] = __fmul_rn(y, y);
        zz[tid]  = __fmul_rn(z, z);
    }
    __syncthreads();

    // Per-slab valid-j half-width dj: valid js = [20-dj, 20+dj], dj = max{d:
    // fadd(xs2[i], ys2[20+d]) <= 36} (monotone -> binary ascent; ys2 symmetric).
    if (tid < NXG) {
        int d = -1;
        #pragma unroll
        for (int step = 16; step; step >>= 1) {
            int nd = d + step;
            if (nd <= 20 && __fadd_rn(xs2[tid], ys2[20 + nd]) <= 36.0f) d = nd;
        }
        djt[tid] = (int8_t)d;
    }
    __syncthreads();

    issue_chunk(0);
    issue_chunk(1);      // 2 chunks in flight; overlaps rowlo build below

    // Per-row valid-k interval [klo, 40-klo] + rowmax preset to NEGF (rows
    // outside the circle are never loaded/reduced -> preset is their value).
    for (int r = tid; r < NROWS; r += THREADS) {
        const int i = div41(r);
        const int j = r - i * NXG;
        const float t2 = __fadd_rn(xs2[i], ys2[j]);
        int d = -1;
        #pragma unroll
        for (int step = 16; step; step >>= 1) {
            int nd = d + step;
            if (nd <= 20 && __fadd_rn(t2, zz[20 + nd]) <= 36.0f) d = nd;
        }
        rowlo[r] = (uint8_t)(20 - d);      // 21 when row entirely outside sphere
        rowmax[r] = NEGF;
    }
    __syncthreads();

    // ---------------- Phase 1: 3-stage ring, 2 slabs/chunk, pair-per-row -----
    for (int ci = 0; ci < NCK; ci++) {
        const int st = ci % NST;
        MBAR_WAIT(mb + (uint32_t)st * 8u, (uint32_t)((ci / NST) & 1));

        const float* B = bufs + (size_t)st * STAGEF;
        const int s0 = 2 * ci, s1v = 2 * ci + 1;
        const int d0 = (int)djt[s0];
        const int d1 = (s1v <= 40) ? (int)djt[s1v] : -1;

        const int slot = tid >> 1;                 // 0..127
        const int half = tid & 1;
        const int sl   = (slot >= 64);             // 0: slab s0, 1: slab s1
        const int rs   = sl ? (slot - 64) : slot;  // row within band
        const int dd   = sl ? d1 : d0;
        const bool ok  = (dd >= 0) && (rs < 2 * dd + 1);
        const int s    = sl ? s1v : s0;
        const int jlo  = 20 - dd;
        const int rsc  = ok ? rs : 0;
        const int r    = ok ? (s * NXG + jlo + rs) : 0;
        const int sft  = (p + s + jlo) & 3;        // == (base + (s*41+jlo)*41) & 3
        const int klo  = (int)rowlo[r];
        const int khi  = 40 - klo;
        const int kb   = half * 21;
        const float* rowp = B + (sl ? SLABBUF : 0) + sft + rsc * NXG + kb;

        float best = NEGF;
        #pragma unroll
        for (int kk = 0; kk < 21; kk++) {
            const int k = kb + kk;                 // k=41 slot: khi<=40 -> excluded
            const float v = rowp[kk];              // in-bounds via SLABBUF slack
            if (k >= klo && k <= khi) best = fmaxf(best, v);
        }
        const float vo = __shfl_down_sync(0xffffffffu, best, 1);
        if (half == 0 && ok)
            rowmax[r] = fmaxf(best, vo);
        __syncthreads();   // stage st fully consumed before refill below

        if (ci + NST - 1 < NCK) issue_chunk(ci + NST - 1);
    }
    __syncthreads();

    // ---------------- Phase 2: K iterations of argmax + local NMS ------------
    int pk_i[KP], pk_j[KP], pk_k[KP];
    int npk = 0;   // replicated across threads (derived from shared data)

    for (int it = 0; it < KP; it++) {
        // Block argmax over rowmax[0..1680], first-occurrence tie-break.
        float bv = -__int_as_float(0x7f800000);
        int   br = 0x7fffffff;
        for (int r = tid; r < NROWS; r += THREADS) {
            float v = rowmax[r];
            if (v > bv) { bv = v; br = r; }        // r ascending: ties keep earlier
        }
        #pragma unroll
        for (int off = 16; off; off >>= 1) {
            float ov = __shfl_xor_sync(0xffffffffu, bv, off);
            int   orr = __shfl_xor_sync(0xffffffffu, br, off);
            if (ov > bv || (ov == bv && orr < br)) { bv = ov; br = orr; }
        }
        if (lane == 0) { swv[w] = bv; swr[w] = br; }
        __syncthreads();
        if (w == 0) {
            float v = (lane < NWARP) ? swv[lane] : -__int_as_float(0x7f800000);
            int   r = (lane < NWARP) ? swr[lane] : 0x7fffffff;
            #pragma unroll
            for (int off = 4; off; off >>= 1) {
                float ov = __shfl_xor_sync(0xffffffffu, v, off);
                int   orr = __shfl_xor_sync(0xffffffffu, r, off);
                if (ov > v || (ov == v && orr < r)) { v = ov; r = orr; }
            }
            if (lane == 0) *s_pick = r;
        }
        __syncthreads();

        const int   pr  = *s_pick;
        const float sc  = rowmax[pr];
        const int   pi  = div41(pr);
        const int   pj  = pr - pi * NXG;
        const bool  valid = sc > VTH;

        // Warp 0 recomputes argmax-k of the picked row (mask + suppression by
        // the npk peaks picked so far; first-k tie-break). L2-hot loads.
        if (w == 0) {
            const float t2 = __fadd_rn(xs2[pi], ys2[pj]);
            const float* rowg = density + base + (size_t)pr * NXG;
            bool in0 = 0 < npk && abs(pi - pk_i[0]) <= SEP && abs(pj - pk_j[0]) <= SEP;
            bool in1 = 1 < npk && abs(pi - pk_i[1]) <= SEP && abs(pj - pk_j[1]) <= SEP;
            bool in2 = 2 < npk && abs(pi - pk_i[2]) <= SEP && abs(pj - pk_j[2]) <= SEP;

            float bvv = NEGF; int bkk = lane;
            {
                const int k = lane;
                bool sup = (__fadd_rn(t2, zz[k]) > 36.0f);
                if (in0 && abs(k - pk_k[0]) <= SEP) sup = true;
                if (in1 && abs(k - pk_k[1]) <= SEP) sup = true;
                if (in2 && abs(k - pk_k[2]) <= SEP) sup = true;
                if (!sup) bvv = __ldg(&rowg[k]);
            }
            const int k2 = lane + 32;
            if (k2 < NXG) {
                bool sup = (__fadd_rn(t2, zz[k2]) > 36.0f);
                if (in0 && abs(k2 - pk_k[0]) <= SEP) sup = true;
                if (in1 && abs(k2 - pk_k[1]) <= SEP) sup = true;
                if (in2 && abs(k2 - pk_k[2]) <= SEP) sup = true;
                if (!sup) {
                    const float v2 = __ldg(&rowg[k2]);
                    if (v2 > bvv) { bvv = v2; bkk = k2; }
                }
            }
            #pragma unroll
            for (int off = 16; off; off >>= 1) {
                const float ov = __shfl_xor_sync(0xffffffffu, bvv, off);
                const int   ok2 = __shfl_xor_sync(0xffffffffu, bkk, off);
                if (ov > bvv || (ov == bvv && ok2 < bkk)) { bvv = ov; bkk = ok2; }
            }
            if (lane == 0) *s_pkk = bkk;
        }
        __syncthreads();

        const int pkk = *s_pkk;
        if (tid == 0) {
            s_ps[it] = sc;
            s_pg[it] = pr * NXG + pkk;
            s_pv[it] = valid ? 1 : 0;
        }
        if (valid) { pk_i[npk] = pi; pk_j[npk] = pj; pk_k[npk] = pkk; npk++; }
        __syncthreads();   // everyone done reading rowmax before rewrite

        if (it == KP - 1) break;

        // Recompute rows intersecting the new peak's Chebyshev ball, applying
        // suppression from ALL picked-so-far peaks. Max value only.
        if (valid) {
            const int i0 = max(pi - SEP, 0), i1 = min(pi + SEP, NXG - 1);
            const int j0 = max(pj - SEP, 0), j1 = min(pj + SEP, NXG - 1);
            const int nj = j1 - j0 + 1;
            const int nr = (i1 - i0 + 1) * nj;
            if (tid < nr) {
                const int i = i0 + tid / nj;
                const int j = j0 + tid % nj;
                const int r = i * NXG + j;
                const float t2 = __fadd_rn(xs2[i], ys2[j]);
                const float* rowg = density + base + (size_t)r * NXG;

                bool in0 = 0 < npk && abs(i - pk_i[0]) <= SEP && abs(j - pk_j[0]) <= SEP;
                bool in1 = 1 < npk && abs(i - pk_i[1]) <= SEP && abs(j - pk_j[1]) <= SEP;
                bool in2 = 2 < npk && abs(i - pk_i[2]) <= SEP && abs(j - pk_j[2]) <= SEP;

                float best = NEGF;
                #pragma unroll
                for (int k = 0; k < NXG; k++) {
                    const float dv = __ldg(&rowg[k]);   // unconditional: enables MLP
                    bool sup = (__fadd_rn(t2, zz[k]) > 36.0f);
                    if (in0 && abs(k - pk_k[0]) <= SEP) sup = true;
                    if (in1 && abs(k - pk_k[1]) <= SEP) sup = true;
                    if (in2 && abs(k - pk_k[2]) <= SEP) sup = true;
                    best = fmaxf(best, sup ? NEGF : dv);
                }
                rowmax[r] = best;
            }
        }
        __syncthreads();
    }

    // ---------------- Epilogue: transform + write outputs --------------------
    // Output layout: coords_local [NC,K,3] | coords_global [NC,K,3] |
    //                scores [NC,K] | mask [NC,K]  (all float32)
    if (tid < KP) {
        const int kk = tid;
        const int n  = p / C;
        const int NC = gridDim.x;

        const float sc    = s_ps[kk];
        const bool  valid = (s_pv[kk] != 0);
        const int   g     = s_pg[kk];

        float x = 0.f, y = 0.f, z = 0.f;
        if (valid) {
            x = grid_xyz[3 * g + 0];
            y = grid_xyz[3 * g + 1];
            z = grid_xyz[3 * g + 2];
        }
        const float nm = node_mask[n];
        const float* R = Rmats + (size_t)n * 9;
        const float* t = tpos  + (size_t)n * 3;
        const float gx = R[0] * x + R[1] * y + R[2] * z + t[0];
        const float gy = R[3] * x + R[4] * y + R[5] * z + t[1];
        const float gz = R[6] * x + R[7] * y + R[8] * z + t[2];

        float* CL = out;
        float* CG = out + (size_t)NC * KP * 3;
        float* SC = out + (size_t)NC * KP * 6;
        float* MS = SC  + (size_t)NC * KP;

        const size_t o3 = ((size_t)p * KP + kk) * 3;
        CL[o3 + 0] = x * nm;  CL[o3 + 1] = y * nm;  CL[o3 + 2] = z * nm;
        CG[o3 + 0] = gx * nm; CG[o3 + 1] = gy * nm; CG[o3 + 2] = gz * nm;
        SC[(size_t)p * KP + kk] = (valid ? sc : NEGF) * nm;
        MS[(size_t)p * KP + kk] = (valid && nm != 0.0f) ? 1.0f : 0.0f;
    }
}

extern "C" void kernel_launch(void* const* d_in, const int* in_sizes, int n_in,
                              void* d_out, int out_size)
{
    // Input order per reference setup_inputs():
    // 0: density [B,N,C,G] f32   1: grid_xyz [G,3] f32   2: sphere_mask (unused)
    // 3: coords_int (unused)     4: Rmats [B,N,3,3] f32  5: tpos [B,N,3] f32
    // 6: node_mask [B,N] f32
    const float* density   = (const float*)d_in[0];
    const float* grid_xyz  = (const float*)d_in[1];
    const float* Rmats     = (const float*)d_in[4];
    const float* tposp     = (const float*)d_in[5];
    const float* node_mask = (const float*)d_in[6];
    float* out = (float*)d_out;

    const int NC = in_sizes[0] / GVOX;      // B*N*C = 512
    const int N  = in_sizes[4] / 9;         // B*N   = 128
    const int C  = NC / N;                  // 4
    (void)n_in; (void)out_size;

    static int smem_set = 0;
    if (!smem_set) {
        cudaFuncSetAttribute(fused_peaks_kernel,
                             cudaFuncAttributeMaxDynamicSharedMemorySize, SM_TOTAL);
        smem_set = 1;
    }
    fused_peaks_kernel<<<NC, THREADS, SM_TOTAL>>>(density, grid_xyz, Rmats, tposp,
                                                  node_mask, out, C);
}

// round 16
// speedup vs baseline: 1.3701x; 1.0446x over previous
#include <cuda_runtime.h>
#include <stdint.h>

// Problem constants (fixed by the reference: NX=41, r_max=6.0, voxel=0.3, K=4, min_sep=3)
#define NXG    41
#define NROWS  (NXG * NXG)       // 1681 rows of 41 voxels
#define GVOX   (NXG * NXG * NXG) // 68921
#define KP     4
#define SEP    3
#define NEGF   (-1.0e9f)
#define VTH    (-1.0e8f)

#define THREADS 256
#define NWARP   8
#define CHROWS  128                            // rows per block chunk
#define NCHUNK  ((NROWS + CHROWS - 1) / CHROWS) // 14
#define CHBUF   (CHROWS * NXG + 8)             // 5256 floats = 21024 B (mult of 16)

// Shared-memory layout (bytes); buffers 16B-aligned.
#define SM_BUF    0                                   // 2 * 21024 = 42048
#define SM_MBAR   (SM_BUF + 2 * CHBUF * 4)            // 16
#define SM_ROWMAX (SM_MBAR + 16)                      // 6724
#define SM_ROWLO  (SM_ROWMAX + NROWS * 4)             // 1684
#define SM_XS2    (SM_ROWLO + 1684)                   // 168
#define SM_YS2    (SM_XS2 + 168)
#define SM_ZZ     (SM_YS2 + 168)
#define SM_SWV    (SM_ZZ + 168)
#define SM_SWR    (SM_SWV + 32)
#define SM_PICK   (SM_SWR + 32)
#define SM_PKK    (SM_PICK + 4)
#define SM_PS     (SM_PKK + 4)
#define SM_PG     (SM_PS + 16)
#define SM_PV     (SM_PG + 16)
#define SM_TOTAL  (SM_PV + 16 + 32)                   // ~51.2 KB -> 4 CTAs/SM

#define CP_ASYNC_4(dst, src) \
    asm volatile("cp.async.ca.shared.global [%0], [%1], 4;"  :: "r"(dst), "l"(src) : "memory")
#define CP_COMMIT()  asm volatile("cp.async.commit_group;" ::: "memory")
#define CP_WAIT0()   asm volatile("cp.async.wait_group 0;" ::: "memory")

#define MBAR_INIT(mbar, cnt) \
    asm volatile("mbarrier.init.shared.b64 [%0], %1;" :: "r"(mbar), "r"(cnt) : "memory")
#define MBAR_EXPECT_TX(mbar, bytes) \
    asm volatile("mbarrier.arrive.expect_tx.shared.b64 _, [%0], %1;" :: "r"(mbar), "r"(bytes) : "memory")
#define FENCE_PROXY_ASYNC() asm volatile("fence.proxy.async.shared::cta;" ::: "memory")

#define MBAR_WAIT(mbar, par) do {                                              \
    uint32_t _m = (mbar); uint32_t _p = (par); uint32_t _d;                    \
    asm volatile("{\n\t.reg .pred p;\n\t"                                      \
        "mbarrier.try_wait.parity.acquire.cta.shared::cta.b64 p, [%1], %2;\n\t"\
        "selp.b32 %0, 1, 0, p;\n\t}"                                           \
        : "=r"(_d) : "r"(_m), "r"(_p) : "memory");                             \
    if (!_d) {                                                                 \
        asm volatile("{\n\t.reg .pred P1;\n\t"                                 \
            "WL_%=:\n\t"                                                       \
            "mbarrier.try_wait.parity.acquire.cta.shared::cta.b64 P1, [%0], %1, 0x989680;\n\t" \
            "@P1 bra.uni WD_%=;\n\t"                                           \
            "bra.uni WL_%=;\n\t"                                               \
            "WD_%=:\n\t}"                                                      \
            :: "r"(_m), "r"(_p) : "memory");                                   \
    }                                                                          \
} while (0)

#define BULK_LD(dst, src, bytes, mbar) \
    asm volatile("cp.async.bulk.shared::cluster.global.mbarrier::complete_tx::bytes " \
                 "[%0], [%1], %2, [%3];" \
                 :: "r"(dst), "l"(src), "r"(bytes), "r"(mbar) : "memory")

static __device__ __forceinline__ uint32_t smem_u32(const void* p) {
    return (uint32_t)__cvta_generic_to_shared(p);
}

// Exact floor(r/41) for 0 <= r < 53773.
static __device__ __forceinline__ int div41(int r) {
    return (int)(((unsigned)r * 51151u) >> 21);
}

// ---------------------------------------------------------------------------
// R9 base (best known: block-wide 21KB TMA bulk chunks, double-buffered) with
// surgical reduce trims: uniform 21-trip overlapping segments [0,20]/[20,40]
// (no tail predicate; k=20 double-counted, max idempotent) and full skip of
// rows entirely outside the sphere (klo==21; rowmax preset to NEGF).
__global__ __launch_bounds__(THREADS, 4)
void fused_peaks_kernel(const float* __restrict__ density,
                        const float* __restrict__ grid_xyz,
                        const float* __restrict__ Rmats,
                        const float* __restrict__ tpos,
                        const float* __restrict__ node_mask,
                        float* __restrict__ out,
                        int C)
{
    extern __shared__ char smem[];
    float*   buf0   = (float*)(smem + SM_BUF);
    float*   buf1   = buf0 + CHBUF;
    float*   rowmax = (float*)(smem + SM_ROWMAX);
    uint8_t* rowlo  = (uint8_t*)(smem + SM_ROWLO);
    float*   xs2    = (float*)(smem + SM_XS2);
    float*   ys2    = (float*)(smem + SM_YS2);
    float*   zz     = (float*)(smem + SM_ZZ);
    float*   swv    = (float*)(smem + SM_SWV);
    int*     swr    = (int*)(smem + SM_SWR);
    int*     s_pick = (int*)(smem + SM_PICK);
    int*     s_pkk  = (int*)(smem + SM_PKK);
    float*   s_ps   = (float*)(smem + SM_PS);
    int*     s_pg   = (int*)(smem + SM_PG);
    int*     s_pv   = (int*)(smem + SM_PV);

    const int tid  = threadIdx.x;
    const int lane = tid & 31;
    const int w    = tid >> 5;
    const int p    = blockIdx.x;
    const size_t base    = (size_t)p * GVOX;        // base % 4 == p % 4
    const size_t total_f = (size_t)gridDim.x * GVOX;
    const uint32_t mb = smem_u32(smem + SM_MBAR);
    const int sft = (int)(base & 3);                // same for every chunk (CHROWS*NXG%4==0)

    // Issue chunk c's 21KB bulk copy (tid 0 path + rare tail by tids<4).
    auto issue_chunk = [&](int c) -> bool {
        const int row0  = c * CHROWS;
        const int nrows = min(CHROWS, NROWS - row0);
        const size_t need_start = base + (size_t)row0 * NXG;
        const size_t srcA = need_start & ~(size_t)3;          // 16B-aligned float idx
        size_t endA = (need_start + (size_t)nrows * NXG + 3) & ~(size_t)3;
        bool tail = false;
        if (endA > total_f) { endA -= 4; tail = true; }       // never when NC%4==0
        const uint32_t bytes = (uint32_t)(endA - srcA) * 4u;
        const uint32_t dstb  = smem_u32((c & 1) ? buf1 : buf0);
        const uint32_t mbar  = mb + (uint32_t)(c & 1) * 8u;
        if (tid == 0) {
            MBAR_EXPECT_TX(mbar, bytes);
            BULK_LD(dstb, density + srcA, bytes, mbar);
        }
        if (tail) {
            const size_t need_end = need_start + (size_t)nrows * NXG;
            const int nrem = (int)(need_end - endA);          // 1..4
            if (tid < nrem)
                CP_ASYNC_4(dstb + (uint32_t)(endA - srcA + tid) * 4u,
                           density + endA + tid);
            CP_COMMIT();
        }
        return tail;
    };

    if (tid == 0) {
        MBAR_INIT(mb, 1);
        MBAR_INIT(mb + 8, 1);
        FENCE_PROXY_ASYNC();
    }
    __syncthreads();          // mbarriers initialized before anyone waits
    bool tail0 = issue_chunk(0);   // overlaps table building below

    // Per-axis squared coords from the ACTUAL grid_xyz input.
    // Sphere test (s<=36.0f) is bit-equivalent to sqrtf(s)<=6.0f under RN.
    if (tid < NXG) {
        float x = grid_xyz[3 * (tid * NXG * NXG) + 0];
        float y = grid_xyz[3 * (tid * NXG) + 1];
        float z = grid_xyz[3 * tid + 2];
        xs2[tid] = __fmul_rn(x, x);
        ys2[tid] = __fmul_rn(y, y);
        zz[tid]  = __fmul_rn(z, z);
    }
    __syncthreads();

    // Per-row valid interval: valid ks = [klo, 40-klo], klo = 20-d where
    // d = max{d: fadd(t2, zz[20+d]) <= 36} (monotone predicate -> binary ascent;
    // zz exactly symmetric about 20 since (-x)*(-x)==x*x).
    // Also preset rowmax to NEGF: rows with klo==21 are skipped in phase 1.
    for (int r = tid; r < NROWS; r += THREADS) {
        const int i = div41(r);
        const int j = r - i * NXG;
        const float t2 = __fadd_rn(xs2[i], ys2[j]);
        int d = -1;
        #pragma unroll
        for (int step = 16; step; step >>= 1) {
            int nd = d + step;
            if (nd <= 20 && __fadd_rn(t2, zz[20 + nd]) <= 36.0f) d = nd;
        }
        rowlo[r] = (uint8_t)(20 - d);      // 21 when row entirely outside sphere
        rowmax[r] = NEGF;
    }
    __syncthreads();

    // ---------------- Phase 1: double-buffered 21KB chunks + row max ---------
    bool tail_cur = tail0;
    for (int c = 0; c < NCHUNK; c++) {
        bool tail_next = false;
        if (c + 1 < NCHUNK) tail_next = issue_chunk(c + 1);

        // Wait chunk c: stage (c&1), parity flips per reuse of that stage.
        MBAR_WAIT(mb + (uint32_t)(c & 1) * 8u, (uint32_t)((c >> 1) & 1));
        if (tail_cur) { CP_WAIT0(); __syncthreads(); }
        tail_cur = tail_next;

        // Pair-per-row: overlapping 21-slot segments [0,20] / [20,40] (k=20
        // counted twice -> idempotent under max). MAX ONLY. Fully-invalid
        // rows (klo==21) skip the scan entirely; preset NEGF is their value.
        const int row0  = c * CHROWS;
        const int nrows = min(CHROWS, NROWS - row0);
        const int lr    = tid >> 1;                  // 0..127
        const int half  = tid & 1;
        const int r     = min(row0 + lr, NROWS - 1);
        const int klo   = (int)rowlo[r];
        const int khi   = 40 - klo;
        const int kb    = half * 20;                 // 0 or 20
        const float* rowp = ((c & 1) ? buf1 : buf0) + sft + lr * NXG + kb;

        float best = NEGF;
        if (klo <= 20) {
            #pragma unroll
            for (int kk = 0; kk < 21; kk++) {
                const int k = kb + kk;
                const float v = rowp[kk];            // in-bounds via CHBUF slack
                if (k >= klo && k <= khi) best = fmaxf(best, v);
            }
        }
        const float vo = __shfl_down_sync(0xffffffffu, best, 1);
        if (half == 0 && lr < nrows && klo <= 20)
            rowmax[row0 + lr] = fmaxf(best, vo);
        __syncthreads();   // all threads done with buffer (c&1) before refill
    }

    // ---------------- Phase 2: K iterations of argmax + local NMS ------------
    int pk_i[KP], pk_j[KP], pk_k[KP];
    int npk = 0;   // replicated across threads (derived from shared data)

    for (int it = 0; it < KP; it++) {
        // Block argmax over rowmax[0..1680], first-occurrence tie-break.
        float bv = -__int_as_float(0x7f800000);
        int   br = 0x7fffffff;
        for (int r = tid; r < NROWS; r += THREADS) {
            float v = rowmax[r];
            if (v > bv) { bv = v; br = r; }        // r ascending: ties keep earlier
        }
        #pragma unroll
        for (int off = 16; off; off >>= 1) {
            float ov = __shfl_xor_sync(0xffffffffu, bv, off);
            int   orr = __shfl_xor_sync(0xffffffffu, br, off);
            if (ov > bv || (ov == bv && orr < br)) { bv = ov; br = orr; }
        }
        if (lane == 0) { swv[w] = bv; swr[w] = br; }
        __syncthreads();
        if (w == 0) {
            float v = (lane < NWARP) ? swv[lane] : -__int_as_float(0x7f800000);
            int   r = (lane < NWARP) ? swr[lane] : 0x7fffffff;
            #pragma unroll
            for (int off = 4; off; off >>= 1) {
                float ov = __shfl_xor_sync(0xffffffffu, v, off);
                int   orr = __shfl_xor_sync(0xffffffffu, r, off);
                if (ov > v || (ov == v && orr < r)) { v = ov; r = orr; }
            }
            if (lane == 0) *s_pick = r;
        }
        __syncthreads();

        const int   pr  = *s_pick;
        const float sc  = rowmax[pr];
        const int   pi  = div41(pr);
        const int   pj  = pr - pi * NXG;
        const bool  valid = sc > VTH;

        // Warp 0 recomputes argmax-k of the picked row (mask + suppression by
        // the npk peaks picked so far; first-k tie-break). L2-hot loads.
        if (w == 0) {
            const float t2 = __fadd_rn(xs2[pi], ys2[pj]);
            const float* rowg = density + base + (size_t)pr * NXG;
            bool in0 = 0 < npk && abs(pi - pk_i[0]) <= SEP && abs(pj - pk_j[0]) <= SEP;
            bool in1 = 1 < npk && abs(pi - pk_i[1]) <= SEP && abs(pj - pk_j[1]) <= SEP;
            bool in2 = 2 < npk && abs(pi - pk_i[2]) <= SEP && abs(pj - pk_j[2]) <= SEP;

            float bvv = NEGF; int bkk = lane;
            {
                const int k = lane;
                bool sup = (__fadd_rn(t2, zz[k]) > 36.0f);
                if (in0 && abs(k - pk_k[0]) <= SEP) sup = true;
                if (in1 && abs(k - pk_k[1]) <= SEP) sup = true;
                if (in2 && abs(k - pk_k[2]) <= SEP) sup = true;
                if (!sup) bvv = __ldg(&rowg[k]);
            }
            const int k2 = lane + 32;
            if (k2 < NXG) {
                bool sup = (__fadd_rn(t2, zz[k2]) > 36.0f);
                if (in0 && abs(k2 - pk_k[0]) <= SEP) sup = true;
                if (in1 && abs(k2 - pk_k[1]) <= SEP) sup = true;
                if (in2 && abs(k2 - pk_k[2]) <= SEP) sup = true;
                if (!sup) {
                    const float v2 = __ldg(&rowg[k2]);
                    if (v2 > bvv) { bvv = v2; bkk = k2; }
                }
            }
            #pragma unroll
            for (int off = 16; off; off >>= 1) {
                const float ov = __shfl_xor_sync(0xffffffffu, bvv, off);
                const int   ok = __shfl_xor_sync(0xffffffffu, bkk, off);
                if (ov > bvv || (ov == bvv && ok < bkk)) { bvv = ov; bkk = ok; }
            }
            if (lane == 0) *s_pkk = bkk;
        }
        __syncthreads();

        const int pkk = *s_pkk;
        if (tid == 0) {
            s_ps[it] = sc;
            s_pg[it] = pr * NXG + pkk;
            s_pv[it] = valid ? 1 : 0;
        }
        if (valid) { pk_i[npk] = pi; pk_j[npk] = pj; pk_k[npk] = pkk; npk++; }
        __syncthreads();   // everyone done reading rowmax before rewrite

        if (it == KP - 1) break;

        // Recompute rows intersecting the new peak's Chebyshev ball, applying
        // suppression from ALL picked-so-far peaks. Max value only.
        if (valid) {
            const int i0 = max(pi - SEP, 0), i1 = min(pi + SEP, NXG - 1);
            const int j0 = max(pj - SEP, 0), j1 = min(pj + SEP, NXG - 1);
            const int nj = j1 - j0 + 1;
            const int nr = (i1 - i0 + 1) * nj;
            if (tid < nr) {
                const int i = i0 + tid / nj;
                const int j = j0 + tid % nj;
                const int r = i * NXG + j;
                const float t2 = __fadd_rn(xs2[i], ys2[j]);
                const float* rowg = density + base + (size_t)r * NXG;

                bool in0 = 0 < npk && abs(i - pk_i[0]) <= SEP && abs(j - pk_j[0]) <= SEP;
                bool in1 = 1 < npk && abs(i - pk_i[1]) <= SEP && abs(j - pk_j[1]) <= SEP;
                bool in2 = 2 < npk && abs(i - pk_i[2]) <= SEP && abs(j - pk_j[2]) <= SEP;

                float best = NEGF;
                #pragma unroll
                for (int k = 0; k < NXG; k++) {
                    const float dv = __ldg(&rowg[k]);   // unconditional: enables MLP
                    bool sup = (__fadd_rn(t2, zz[k]) > 36.0f);
                    if (in0 && abs(k - pk_k[0]) <= SEP) sup = true;
                    if (in1 && abs(k - pk_k[1]) <= SEP) sup = true;
                    if (in2 && abs(k - pk_k[2]) <= SEP) sup = true;
                    best = fmaxf(best, sup ? NEGF : dv);
                }
                rowmax[r] = best;
            }
        }
        __syncthreads();
    }

    // ---------------- Epilogue: transform + write outputs --------------------
    // Output layout: coords_local [NC,K,3] | coords_global [NC,K,3] |
    //                scores [NC,K] | mask [NC,K]  (all float32)
    if (tid < KP) {
        const int kk = tid;
        const int n  = p / C;
        const int NC = gridDim.x;

        const float sc    = s_ps[kk];
        const bool  valid = (s_pv[kk] != 0);
        const int   g     = s_pg[kk];

        float x = 0.f, y = 0.f, z = 0.f;
        if (valid) {
            x = grid_xyz[3 * g + 0];
            y = grid_xyz[3 * g + 1];
            z = grid_xyz[3 * g + 2];
        }
        const float nm = node_mask[n];
        const float* R = Rmats + (size_t)n * 9;
        const float* t = tpos  + (size_t)n * 3;
        const float gx = R[0] * x + R[1] * y + R[2] * z + t[0];
        const float gy = R[3] * x + R[4] * y + R[5] * z + t[1];
        const float gz = R[6] * x + R[7] * y + R[8] * z + t[2];

        float* CL = out;
        float* CG = out + (size_t)NC * KP * 3;
        float* SC = out + (size_t)NC * KP * 6;
        float* MS = SC  + (size_t)NC * KP;

        const size_t o3 = ((size_t)p * KP + kk) * 3;
        CL[o3 + 0] = x * nm;  CL[o3 + 1] = y * nm;  CL[o3 + 2] = z * nm;
        CG[o3 + 0] = gx * nm; CG[o3 + 1] = gy * nm; CG[o3 + 2] = gz * nm;
        SC[(size_t)p * KP + kk] = (valid ? sc : NEGF) * nm;
        MS[(size_t)p * KP + kk] = (valid && nm != 0.0f) ? 1.0f : 0.0f;
    }
}

extern "C" void kernel_launch(void* const* d_in, const int* in_sizes, int n_in,
                              void* d_out, int out_size)
{
    // Input order per reference setup_inputs():
    // 0: density [B,N,C,G] f32   1: grid_xyz [G,3] f32   2: sphere_mask (unused)
    // 3: coords_int (unused)     4: Rmats [B,N,3,3] f32  5: tpos [B,N,3] f32
    // 6: node_mask [B,N] f32
    const float* density   = (const float*)d_in[0];
    const float* grid_xyz  = (const float*)d_in[1];
    const float* Rmats     = (const float*)d_in[4];
    const float* tposp     = (const float*)d_in[5];
    const float* node_mask = (const float*)d_in[6];
    float* out = (float*)d_out;

    const int NC = in_sizes[0] / GVOX;      // B*N*C = 512
    const int N  = in_sizes[4] / 9;         // B*N   = 128
    const int C  = NC / N;                  // 4
    (void)n_in; (void)out_size;

    static int smem_set = 0;
    if (!smem_set) {
        cudaFuncSetAttribute(fused_peaks_kernel,
                             cudaFuncAttributeMaxDynamicSharedMemorySize, SM_TOTAL);
        smem_set = 1;
    }
    fused_peaks_kernel<<<NC, THREADS, SM_TOTAL>>>(density, grid_xyz, Rmats, tposp,
                                                  node_mask, out, C);
}